// round 12
// baseline (speedup 1.0000x reference)
#include <cuda_runtime.h>
#include <math.h>

#define BATCH 1024
#define HID   512
#define VOC   512
#define TSTEPS 64
#define FH    2048   // 4*HID

// -------- persistent device scratch (no allocs allowed) --------
__device__ float g_EProj[VOC * FH];                       // emb @ W_ih^T + bias
__device__ float g_h[2][BATCH * HID];                     // double-buffered hidden
__device__ float g_c[BATCH * HID];                        // cell state
__device__ unsigned long long g_key[TSTEPS + 1][BATCH];   // per-step argmax keys
__device__ int   g_d1[TSTEPS + 1][8];                     // sync1: keys published
__device__ int   g_d2[TSTEPS + 1][8];                     // sync2: h written (arrive-only)

// -------- packed fp32x2 helpers (sm_103a FFMA2 path) --------
__device__ __forceinline__ unsigned long long pack2(float x, float y) {
    unsigned long long r;
    asm("mov.b64 %0, {%1, %2};" : "=l"(r) : "f"(x), "f"(y));
    return r;
}
__device__ __forceinline__ float2 unpack2(unsigned long long v) {
    float2 r;
    asm("mov.b64 {%0, %1}, %2;" : "=f"(r.x), "=f"(r.y) : "l"(v));
    return r;
}
__device__ __forceinline__ void fma2(unsigned long long& d, unsigned long long a,
                                     unsigned long long b) {
    asm("fma.rn.f32x2 %0, %1, %2, %3;" : "=l"(d) : "l"(a), "l"(b), "l"(d));
}
__device__ __forceinline__ float sigf(float x) { return 0.5f * tanhf(0.5f * x) + 0.5f; }

__device__ __forceinline__ unsigned int fmono(float v) {
    unsigned int u = __float_as_uint(v);
    return u ^ ((unsigned int)((int)u >> 31) | 0x80000000u);
}
__device__ __forceinline__ unsigned long long mkkey(float v, int idx) {
    return ((unsigned long long)fmono(v) << 32) | (0xFFFFFFFFu - (unsigned)idx);
}

// -------- L1-bypass / reduction accessors (persistent kernel) --------
__device__ __forceinline__ float4 ldcg_f4(const float* p) {
    float4 v;
    asm volatile("ld.global.cg.v4.f32 {%0,%1,%2,%3}, [%4];"
                 : "=f"(v.x), "=f"(v.y), "=f"(v.z), "=f"(v.w) : "l"(p));
    return v;
}
__device__ __forceinline__ void stcg_f2(float* p, float x, float y) {
    asm volatile("st.global.cg.v2.f32 [%0], {%1,%2};" :: "l"(p), "f"(x), "f"(y)
                 : "memory");
}
__device__ __forceinline__ int ldcv_i32(const int* p) {
    int v;
    asm volatile("ld.global.cv.s32 %0, [%1];" : "=r"(v) : "l"(p));
    return v;
}
__device__ __forceinline__ unsigned long long ldcv_u64(const unsigned long long* p) {
    unsigned long long v;
    asm volatile("ld.global.cv.u64 %0, [%1];" : "=l"(v) : "l"(p));
    return v;
}
__device__ __forceinline__ void redmax_u64(unsigned long long* p, unsigned long long v) {
    asm volatile("red.global.max.u64 [%0], %1;" :: "l"(p), "l"(v) : "memory");
}

// ============================================================
// init: h0/c0, zero all key buffers and sync counters
// ============================================================
__global__ void __launch_bounds__(256) init_kernel(const float* __restrict__ eh,
                                                   const float* __restrict__ ec) {
    int i = blockIdx.x * blockDim.x + threadIdx.x;
    int stride = gridDim.x * blockDim.x;
    for (int k = i; k < BATCH * HID; k += stride) {
        g_h[0][k] = eh[k];
        g_c[k]    = ec[k];
    }
    for (int k = i; k < (TSTEPS + 1) * BATCH; k += stride)
        ((unsigned long long*)g_key)[k] = 0ull;
    if (i < (TSTEPS + 1) * 8) {
        ((int*)g_d1)[i] = 0;
        ((int*)g_d2)[i] = 0;
    }
}

// ============================================================
// E_proj precompute (R2 proven, unchanged): 256 threads
// ============================================================
struct __align__(16) SmemT {
    float As[16][128];
    float Bs[16][128];
};

__global__ void __launch_bounds__(256) eproj_kernel(
    const float* __restrict__ emb, const float* __restrict__ Wih,
    const float* __restrict__ b_ih, const float* __restrict__ b_hh)
{
    __shared__ SmemT s;
    int tid = threadIdx.x, bx = blockIdx.x, by = blockIdx.y;
    int ty = tid >> 4, tx = tid & 15;
    int rl = tid & 127, kh = (tid >> 7) * 8;
    int bg = rl >> 5, bj = rl & 31;

    unsigned long long acc[4][8];
    #pragma unroll
    for (int g = 0; g < 4; g++)
        #pragma unroll
        for (int m = 0; m < 8; m++) acc[g][m] = 0ULL;

    const float* aPtr = emb + (size_t)(by * 128 + rl) * HID + kh;
    const float* bPtr = Wih + (size_t)(bg * HID + bx * 32 + bj) * HID + kh;

    float4 aR0 = *(const float4*)(aPtr);
    float4 aR1 = *(const float4*)(aPtr + 4);
    float4 bR0 = *(const float4*)(bPtr);
    float4 bR1 = *(const float4*)(bPtr + 4);

    #pragma unroll 1
    for (int tt = 0; tt < HID / 16; tt++) {
        s.As[kh + 0][rl] = aR0.x;  s.As[kh + 1][rl] = aR0.y;
        s.As[kh + 2][rl] = aR0.z;  s.As[kh + 3][rl] = aR0.w;
        s.As[kh + 4][rl] = aR1.x;  s.As[kh + 5][rl] = aR1.y;
        s.As[kh + 6][rl] = aR1.z;  s.As[kh + 7][rl] = aR1.w;
        s.Bs[kh + 0][rl] = bR0.x;  s.Bs[kh + 1][rl] = bR0.y;
        s.Bs[kh + 2][rl] = bR0.z;  s.Bs[kh + 3][rl] = bR0.w;
        s.Bs[kh + 4][rl] = bR1.x;  s.Bs[kh + 5][rl] = bR1.y;
        s.Bs[kh + 6][rl] = bR1.z;  s.Bs[kh + 7][rl] = bR1.w;
        __syncthreads();

        if (tt + 1 < HID / 16) {
            int k0 = (tt + 1) * 16;
            aR0 = *(const float4*)(aPtr + k0);
            aR1 = *(const float4*)(aPtr + k0 + 4);
            bR0 = *(const float4*)(bPtr + k0);
            bR1 = *(const float4*)(bPtr + k0 + 4);
        }

        #pragma unroll
        for (int kk = 0; kk < 16; kk++) {
            float4 a0 = *(const float4*)&s.As[kk][ty * 8];
            float4 a1 = *(const float4*)&s.As[kk][ty * 8 + 4];
            unsigned long long A0 = pack2(a0.x, a0.x), A1 = pack2(a0.y, a0.y);
            unsigned long long A2 = pack2(a0.z, a0.z), A3 = pack2(a0.w, a0.w);
            unsigned long long A4 = pack2(a1.x, a1.x), A5 = pack2(a1.y, a1.y);
            unsigned long long A6 = pack2(a1.z, a1.z), A7 = pack2(a1.w, a1.w);
            #pragma unroll
            for (int g = 0; g < 4; g++) {
                unsigned long long bv =
                    *(const unsigned long long*)&s.Bs[kk][g * 32 + tx * 2];
                fma2(acc[g][0], A0, bv);  fma2(acc[g][1], A1, bv);
                fma2(acc[g][2], A2, bv);  fma2(acc[g][3], A3, bv);
                fma2(acc[g][4], A4, bv);  fma2(acc[g][5], A5, bv);
                fma2(acc[g][6], A6, bv);  fma2(acc[g][7], A7, bv);
            }
        }
        __syncthreads();
    }

    int jBase = bx * 32 + tx * 2;
    #pragma unroll
    for (int m = 0; m < 8; m++) {
        int v = by * 128 + ty * 8 + m;
        #pragma unroll
        for (int g = 0; g < 4; g++) {
            float2 r = unpack2(acc[g][m]);
            int n0 = g * HID + jBase;
            r.x += b_ih[n0]     + b_hh[n0];
            r.y += b_ih[n0 + 1] + b_hh[n0 + 1];
            *(float2*)&g_EProj[(size_t)v * FH + n0] = r;
        }
    }
}

// ============================================================
// Persistent fused step kernel (R11 + relaxed sync2 + per-step keys):
//   per step: B/W tile-0 staged BEFORE the h(t) consumer-wait (weights are
//   step-invariant); mainloop unchanged (R9); keys via REDG (no return);
//   sync1 barrier (true reduction); LSTM epilogue; sync2 arrive-ONLY.
// grid (16 jx, 8 by) = 128 CTAs (all resident), 256 threads.
// ============================================================
__global__ void __launch_bounds__(256, 1) step_persist_kernel(
    const float* __restrict__ Whh, const float* __restrict__ Wout,
    const float* __restrict__ bo, float* __restrict__ out)
{
    __shared__ __align__(16) float As[2][16][128];
    __shared__ __align__(16) float Bs[2][16][128];
    __shared__ __align__(8)  float Ws[2][16][32];

    int tid = threadIdx.x, bx = blockIdx.x, by = blockIdx.y;

    int ty = tid >> 4, tx = tid & 15;
    int rl = tid & 127, kh = (tid >> 7) * 8;
    int bg = rl >> 5, bj = rl & 31;
    int wrow = tid & 31, wk = (tid >> 5) * 2;   // Wout loader mapping

    const float* bPtr = Whh  + (size_t)(bg * HID + bx * 32 + bj) * HID + kh;
    const float* wPtr = Wout + (size_t)(bx * 32 + wrow) * HID + wk;
    int jBase = bx * 32 + tx * 2;
    int colb = jBase;
    float2 bb = *(const float2*)&bo[colb];

    #pragma unroll 1
    for (int t = 0; t <= TSTEPS; t++) {
        int parity = t & 1;
        const float* h_in  = g_h[parity];
        float*       h_out = g_h[parity ^ 1];
        float* out_prev = out + (size_t)((t > 0) ? (t - 1) : 0) * BATCH * VOC;

        unsigned long long acc[4][8];
        unsigned long long accw[8];
        #pragma unroll
        for (int g = 0; g < 4; g++)
            #pragma unroll
            for (int m = 0; m < 8; m++) acc[g][m] = 0ULL;
        #pragma unroll
        for (int m = 0; m < 8; m++) accw[m] = 0ULL;

        // ---- stage B/W tile 0 (no dependency on h) BEFORE the wait ----
        float4 bR0 = *(const float4*)(bPtr);
        float4 bR1 = *(const float4*)(bPtr + 4);
        float2 wR  = *(const float2*)(wPtr);
        Bs[0][kh + 0][rl] = bR0.x;  Bs[0][kh + 1][rl] = bR0.y;
        Bs[0][kh + 2][rl] = bR0.z;  Bs[0][kh + 3][rl] = bR0.w;
        Bs[0][kh + 4][rl] = bR1.x;  Bs[0][kh + 5][rl] = bR1.y;
        Bs[0][kh + 6][rl] = bR1.z;  Bs[0][kh + 7][rl] = bR1.w;
        Ws[0][wk + 0][wrow] = wR.x;
        Ws[0][wk + 1][wrow] = wR.y;

        // ---- consumer-side wait: h(t) of this b-tile fully written ----
        if (t > 0) {
            if (tid == 0) {
                while (ldcv_i32(&g_d2[t - 1][by]) < 16) __nanosleep(16);
            }
            __threadfence();
            __syncthreads();
        }

        // ---- now load & stage A tile 0 ----
        const float* aPtr = h_in + (size_t)(by * 128 + rl) * HID + kh;
        float4 aR0 = ldcg_f4(aPtr);
        float4 aR1 = ldcg_f4(aPtr + 4);
        As[0][kh + 0][rl] = aR0.x;  As[0][kh + 1][rl] = aR0.y;
        As[0][kh + 2][rl] = aR0.z;  As[0][kh + 3][rl] = aR0.w;
        As[0][kh + 4][rl] = aR1.x;  As[0][kh + 5][rl] = aR1.y;
        As[0][kh + 6][rl] = aR1.z;  As[0][kh + 7][rl] = aR1.w;

        #pragma unroll 1
        for (int tt = 0; tt < HID / 16; tt++) {
            __syncthreads();           // buf filled -> visible; buf^1 free
            int buf = tt & 1;
            if (tt + 1 < HID / 16) {   // prefetch next tile from global
                int k0 = (tt + 1) * 16;
                aR0 = ldcg_f4(aPtr + k0);
                aR1 = ldcg_f4(aPtr + k0 + 4);
                bR0 = *(const float4*)(bPtr + k0);
                bR1 = *(const float4*)(bPtr + k0 + 4);
                wR  = *(const float2*)(wPtr + k0);
            }

            #pragma unroll
            for (int kk = 0; kk < 16; kk++) {
                float4 a0 = *(const float4*)&As[buf][kk][ty * 8];
                float4 a1 = *(const float4*)&As[buf][kk][ty * 8 + 4];
                unsigned long long A0 = pack2(a0.x, a0.x), A1 = pack2(a0.y, a0.y);
                unsigned long long A2 = pack2(a0.z, a0.z), A3 = pack2(a0.w, a0.w);
                unsigned long long A4 = pack2(a1.x, a1.x), A5 = pack2(a1.y, a1.y);
                unsigned long long A6 = pack2(a1.z, a1.z), A7 = pack2(a1.w, a1.w);
                #pragma unroll
                for (int g = 0; g < 4; g++) {
                    unsigned long long bv =
                        *(const unsigned long long*)&Bs[buf][kk][g * 32 + tx * 2];
                    fma2(acc[g][0], A0, bv);  fma2(acc[g][1], A1, bv);
                    fma2(acc[g][2], A2, bv);  fma2(acc[g][3], A3, bv);
                    fma2(acc[g][4], A4, bv);  fma2(acc[g][5], A5, bv);
                    fma2(acc[g][6], A6, bv);  fma2(acc[g][7], A7, bv);
                }
                unsigned long long wv =
                    *(const unsigned long long*)&Ws[buf][kk][tx * 2];
                fma2(accw[0], A0, wv);  fma2(accw[1], A1, wv);
                fma2(accw[2], A2, wv);  fma2(accw[3], A3, wv);
                fma2(accw[4], A4, wv);  fma2(accw[5], A5, wv);
                fma2(accw[6], A6, wv);  fma2(accw[7], A7, wv);
            }

            if (tt + 1 < HID / 16) {   // stage next tile into the other buffer
                int nb = buf ^ 1;
                As[nb][kh + 0][rl] = aR0.x;  As[nb][kh + 1][rl] = aR0.y;
                As[nb][kh + 2][rl] = aR0.z;  As[nb][kh + 3][rl] = aR0.w;
                As[nb][kh + 4][rl] = aR1.x;  As[nb][kh + 5][rl] = aR1.y;
                As[nb][kh + 6][rl] = aR1.z;  As[nb][kh + 7][rl] = aR1.w;
                Bs[nb][kh + 0][rl] = bR0.x;  Bs[nb][kh + 1][rl] = bR0.y;
                Bs[nb][kh + 2][rl] = bR0.z;  Bs[nb][kh + 3][rl] = bR0.w;
                Bs[nb][kh + 4][rl] = bR1.x;  Bs[nb][kh + 5][rl] = bR1.y;
                Bs[nb][kh + 6][rl] = bR1.z;  Bs[nb][kh + 7][rl] = bR1.w;
                Ws[nb][wk + 0][wrow] = wR.x;
                Ws[nb][wk + 1][wrow] = wR.y;
            }
        }

        // ---------- logits epilogue: bias, store out[t-1], keys via REDG ----
        #pragma unroll
        for (int m = 0; m < 8; m++) {
            int b = by * 128 + ty * 8 + m;
            float2 lw = unpack2(accw[m]);
            float x0 = lw.x + bb.x;
            float x1 = lw.y + bb.y;
            *(float2*)&out_prev[(size_t)b * VOC + colb] = make_float2(x0, x1);

            unsigned long long key = mkkey(x0, colb);
            unsigned long long k1  = mkkey(x1, colb + 1);
            if (k1 > key) key = k1;
            #pragma unroll
            for (int off = 8; off > 0; off >>= 1) {
                unsigned long long o = __shfl_down_sync(0xFFFFFFFFu, key, off, 16);
                if (o > key) key = o;
            }
            if (tx == 0) redmax_u64(&g_key[t][b], key);
        }

        // ---------- sync1: keys from all 16 jx CTAs of this b-tile ----------
        __threadfence();
        __syncthreads();
        if (tid == 0) {
            atomicAdd(&g_d1[t][by], 1);
            while (ldcv_i32(&g_d1[t][by]) < 16) __nanosleep(16);
        }
        __syncthreads();

        // ---------- LSTM epilogue, idx decoded from fresh keys --------------
        #pragma unroll
        for (int m = 0; m < 8; m++) {
            int b = by * 128 + ty * 8 + m;
            unsigned int row;
            if (t == 0) {
                row = 0;  // SOS
            } else {
                unsigned long long kv = ldcv_u64(&g_key[t][b]);
                row = 0xFFFFFFFFu - (unsigned int)kv;
            }
            const float* ep = g_EProj + (size_t)row * FH + jBase;

            float2 gi = unpack2(acc[0][m]);
            float2 gf = unpack2(acc[1][m]);
            float2 gg = unpack2(acc[2][m]);
            float2 go = unpack2(acc[3][m]);
            float2 e;
            e = *(const float2*)(ep +    0); gi.x += e.x; gi.y += e.y;
            e = *(const float2*)(ep +  512); gf.x += e.x; gf.y += e.y;
            e = *(const float2*)(ep + 1024); gg.x += e.x; gg.y += e.y;
            e = *(const float2*)(ep + 1536); go.x += e.x; go.y += e.y;

            float2 cold = *(const float2*)&g_c[(size_t)b * HID + jBase];
            float2 cn, hn;
            {
                float i_ = sigf(gi.x), f_ = sigf(gf.x), gv = tanhf(gg.x), o_ = sigf(go.x);
                cn.x = f_ * cold.x + i_ * gv;
                hn.x = o_ * tanhf(cn.x);
            }
            {
                float i_ = sigf(gi.y), f_ = sigf(gf.y), gv = tanhf(gg.y), o_ = sigf(go.y);
                cn.y = f_ * cold.y + i_ * gv;
                hn.y = o_ * tanhf(cn.y);
            }
            *(float2*)&g_c[(size_t)b * HID + jBase] = cn;   // CTA-private
            stcg_f2(&h_out[(size_t)b * HID + jBase], hn.x, hn.y);  // cross-SM
        }

        // ---------- sync2: ARRIVE-ONLY (consumers wait at next step top) ----
        __threadfence();
        __syncthreads();
        if (tid == 0) atomicAdd(&g_d2[t][by], 1);
    }
}

// ============================================================
// launch: init, eproj, ONE persistent kernel for all 65 steps
// ============================================================
extern "C" void kernel_launch(void* const* d_in, const int* in_sizes, int n_in,
                              void* d_out, int out_size)
{
    int i = 0;
    while (i < n_in && in_sizes[i] != BATCH * HID) i++;
    const float* enc_h = (const float*)d_in[i];
    const float* enc_c = (const float*)d_in[i + 1];
    const float* emb   = (const float*)d_in[i + 2];
    const float* W_ih  = (const float*)d_in[i + 3];
    const float* W_hh  = (const float*)d_in[i + 4];
    const float* b_ih  = (const float*)d_in[i + 5];
    const float* b_hh  = (const float*)d_in[i + 6];
    const float* W_out = (const float*)d_in[i + 7];
    const float* b_out = (const float*)d_in[i + 8];
    float* out = (float*)d_out;

    init_kernel<<<512, 256>>>(enc_h, enc_c);
    eproj_kernel<<<dim3(16, 4), 256>>>(emb, W_ih, b_ih, b_hh);
    step_persist_kernel<<<dim3(16, 8), 256>>>(W_hh, W_out, b_out, out);
}

// round 13
// speedup vs baseline: 1.7908x; 1.7908x over previous
#include <cuda_runtime.h>
#include <math.h>

#define BATCH 1024
#define HID   512
#define VOC   512
#define TSTEPS 64
#define FH    2048   // 4*HID

// -------- persistent device scratch (no allocs allowed) --------
__device__ float g_EProj[VOC * FH];            // embedding @ W_ih^T + bias, 4MB
__device__ float g_h[2][BATCH * HID];          // double-buffered hidden state
__device__ float g_c[BATCH * HID];             // cell state
__device__ unsigned long long g_key[2][BATCH]; // packed (value|~idx) argmax keys
__device__ int   g_d1[TSTEPS + 1][8];          // sync1: keys published
__device__ int   g_d2[TSTEPS + 1][8];          // sync2: h written

// -------- packed fp32x2 helpers (sm_103a FFMA2 path) --------
__device__ __forceinline__ unsigned long long pack2(float x, float y) {
    unsigned long long r;
    asm("mov.b64 %0, {%1, %2};" : "=l"(r) : "f"(x), "f"(y));
    return r;
}
__device__ __forceinline__ float2 unpack2(unsigned long long v) {
    float2 r;
    asm("mov.b64 {%0, %1}, %2;" : "=f"(r.x), "=f"(r.y) : "l"(v));
    return r;
}
__device__ __forceinline__ void fma2(unsigned long long& d, unsigned long long a,
                                     unsigned long long b) {
    asm("fma.rn.f32x2 %0, %1, %2, %3;" : "=l"(d) : "l"(a), "l"(b), "l"(d));
}

// fast activations (MUFU.EX2/RCP path): abs err ~1e-7..1e-6, vs 5e-4 for HW tanh
__device__ __forceinline__ float sigfast(float x) {
    float e = __expf(-x);
    return __fdividef(1.0f, 1.0f + e);
}
__device__ __forceinline__ float tanhfast(float x) {
    float e = __expf(-2.0f * x);
    return __fdividef(2.0f, 1.0f + e) - 1.0f;
}

__device__ __forceinline__ unsigned int fmono(float v) {
    unsigned int u = __float_as_uint(v);
    return u ^ ((unsigned int)((int)u >> 31) | 0x80000000u);
}
__device__ __forceinline__ unsigned long long mkkey(float v, int idx) {
    return ((unsigned long long)fmono(v) << 32) | (0xFFFFFFFFu - (unsigned)idx);
}

// -------- L1-bypass accessors (persistent kernel: no per-launch L1 flush) ----
__device__ __forceinline__ float4 ldcg_f4(const float* p) {
    float4 v;
    asm volatile("ld.global.cg.v4.f32 {%0,%1,%2,%3}, [%4];"
                 : "=f"(v.x), "=f"(v.y), "=f"(v.z), "=f"(v.w) : "l"(p));
    return v;
}
__device__ __forceinline__ void stcg_f2(float* p, float x, float y) {
    asm volatile("st.global.cg.v2.f32 [%0], {%1,%2};" :: "l"(p), "f"(x), "f"(y)
                 : "memory");
}
__device__ __forceinline__ int ldcv_i32(const int* p) {
    int v;
    asm volatile("ld.global.cv.s32 %0, [%1];" : "=r"(v) : "l"(p));
    return v;
}
__device__ __forceinline__ unsigned long long ldcv_u64(const unsigned long long* p) {
    unsigned long long v;
    asm volatile("ld.global.cv.u64 %0, [%1];" : "=l"(v) : "l"(p));
    return v;
}

// ============================================================
// init: h0/c0, zero key buffers and sync counters
// ============================================================
__global__ void __launch_bounds__(256) init_kernel(const float* __restrict__ eh,
                                                   const float* __restrict__ ec) {
    int i = blockIdx.x * blockDim.x + threadIdx.x;
    int stride = gridDim.x * blockDim.x;
    for (int k = i; k < BATCH * HID; k += stride) {
        g_h[0][k] = eh[k];
        g_c[k]    = ec[k];
    }
    if (i < BATCH) {
        g_key[0][i] = 0ull;
        g_key[1][i] = 0ull;
    }
    if (i < (TSTEPS + 1) * 8) {
        ((int*)g_d1)[i] = 0;
        ((int*)g_d2)[i] = 0;
    }
}

// ============================================================
// E_proj precompute (R2 proven, unchanged): 256 threads
// ============================================================
struct __align__(16) SmemT {
    float As[16][128];
    float Bs[16][128];
};

__global__ void __launch_bounds__(256) eproj_kernel(
    const float* __restrict__ emb, const float* __restrict__ Wih,
    const float* __restrict__ b_ih, const float* __restrict__ b_hh)
{
    __shared__ SmemT s;
    int tid = threadIdx.x, bx = blockIdx.x, by = blockIdx.y;
    int ty = tid >> 4, tx = tid & 15;
    int rl = tid & 127, kh = (tid >> 7) * 8;
    int bg = rl >> 5, bj = rl & 31;

    unsigned long long acc[4][8];
    #pragma unroll
    for (int g = 0; g < 4; g++)
        #pragma unroll
        for (int m = 0; m < 8; m++) acc[g][m] = 0ULL;

    const float* aPtr = emb + (size_t)(by * 128 + rl) * HID + kh;
    const float* bPtr = Wih + (size_t)(bg * HID + bx * 32 + bj) * HID + kh;

    float4 aR0 = *(const float4*)(aPtr);
    float4 aR1 = *(const float4*)(aPtr + 4);
    float4 bR0 = *(const float4*)(bPtr);
    float4 bR1 = *(const float4*)(bPtr + 4);

    #pragma unroll 1
    for (int tt = 0; tt < HID / 16; tt++) {
        s.As[kh + 0][rl] = aR0.x;  s.As[kh + 1][rl] = aR0.y;
        s.As[kh + 2][rl] = aR0.z;  s.As[kh + 3][rl] = aR0.w;
        s.As[kh + 4][rl] = aR1.x;  s.As[kh + 5][rl] = aR1.y;
        s.As[kh + 6][rl] = aR1.z;  s.As[kh + 7][rl] = aR1.w;
        s.Bs[kh + 0][rl] = bR0.x;  s.Bs[kh + 1][rl] = bR0.y;
        s.Bs[kh + 2][rl] = bR0.z;  s.Bs[kh + 3][rl] = bR0.w;
        s.Bs[kh + 4][rl] = bR1.x;  s.Bs[kh + 5][rl] = bR1.y;
        s.Bs[kh + 6][rl] = bR1.z;  s.Bs[kh + 7][rl] = bR1.w;
        __syncthreads();

        if (tt + 1 < HID / 16) {
            int k0 = (tt + 1) * 16;
            aR0 = *(const float4*)(aPtr + k0);
            aR1 = *(const float4*)(aPtr + k0 + 4);
            bR0 = *(const float4*)(bPtr + k0);
            bR1 = *(const float4*)(bPtr + k0 + 4);
        }

        #pragma unroll
        for (int kk = 0; kk < 16; kk++) {
            float4 a0 = *(const float4*)&s.As[kk][ty * 8];
            float4 a1 = *(const float4*)&s.As[kk][ty * 8 + 4];
            unsigned long long A0 = pack2(a0.x, a0.x), A1 = pack2(a0.y, a0.y);
            unsigned long long A2 = pack2(a0.z, a0.z), A3 = pack2(a0.w, a0.w);
            unsigned long long A4 = pack2(a1.x, a1.x), A5 = pack2(a1.y, a1.y);
            unsigned long long A6 = pack2(a1.z, a1.z), A7 = pack2(a1.w, a1.w);
            #pragma unroll
            for (int g = 0; g < 4; g++) {
                unsigned long long bv =
                    *(const unsigned long long*)&s.Bs[kk][g * 32 + tx * 2];
                fma2(acc[g][0], A0, bv);  fma2(acc[g][1], A1, bv);
                fma2(acc[g][2], A2, bv);  fma2(acc[g][3], A3, bv);
                fma2(acc[g][4], A4, bv);  fma2(acc[g][5], A5, bv);
                fma2(acc[g][6], A6, bv);  fma2(acc[g][7], A7, bv);
            }
        }
        __syncthreads();
    }

    int jBase = bx * 32 + tx * 2;
    #pragma unroll
    for (int m = 0; m < 8; m++) {
        int v = by * 128 + ty * 8 + m;
        #pragma unroll
        for (int g = 0; g < 4; g++) {
            float2 r = unpack2(acc[g][m]);
            int n0 = g * HID + jBase;
            r.x += b_ih[n0]     + b_hh[n0];
            r.y += b_ih[n0 + 1] + b_hh[n0 + 1];
            *(float2*)&g_EProj[(size_t)v * FH + n0] = r;
        }
    }
}

// ============================================================
// Persistent fused step kernel (R11 structure, verbatim sync protocol):
// per step t: zero next keys; stage tile 0; mainloop (R9); logits epilogue
// + keys (skipped at t=0); sync1 (skipped at t=0); LSTM epilogue + sync2
// (skipped at t=TSTEPS). Fast activations in LSTM epilogue.
// grid (16 jx, 8 by) = 128 CTAs (all resident), 256 threads.
// ============================================================
__global__ void __launch_bounds__(256, 1) step_persist_kernel(
    const float* __restrict__ Whh, const float* __restrict__ Wout,
    const float* __restrict__ bo, float* __restrict__ out)
{
    __shared__ __align__(16) float As[2][16][128];
    __shared__ __align__(16) float Bs[2][16][128];
    __shared__ __align__(8)  float Ws[2][16][32];

    int tid = threadIdx.x, bx = blockIdx.x, by = blockIdx.y;

    int ty = tid >> 4, tx = tid & 15;
    int rl = tid & 127, kh = (tid >> 7) * 8;
    int bg = rl >> 5, bj = rl & 31;
    int wrow = tid & 31, wk = (tid >> 5) * 2;   // Wout loader mapping

    const float* bPtr = Whh  + (size_t)(bg * HID + bx * 32 + bj) * HID + kh;
    const float* wPtr = Wout + (size_t)(bx * 32 + wrow) * HID + wk;
    int jBase = bx * 32 + tx * 2;
    int colb = jBase;
    float2 bb = *(const float2*)&bo[colb];

    #pragma unroll 1
    for (int t = 0; t <= TSTEPS; t++) {
        int parity = t & 1;
        const float* h_in  = g_h[parity];
        float*       h_out = g_h[parity ^ 1];
        float* out_prev = out + (size_t)((t > 0) ? (t - 1) : 0) * BATCH * VOC;

        // zero the key buffer the NEXT step will use (skip on final step)
        if (t < TSTEPS && bx == 0 && tid < 128)
            g_key[parity ^ 1][by * 128 + tid] = 0ull;

        unsigned long long acc[4][8];
        unsigned long long accw[8];
        #pragma unroll
        for (int g = 0; g < 4; g++)
            #pragma unroll
            for (int m = 0; m < 8; m++) acc[g][m] = 0ULL;
        #pragma unroll
        for (int m = 0; m < 8; m++) accw[m] = 0ULL;

        const float* aPtr = h_in + (size_t)(by * 128 + rl) * HID + kh;

        float4 aR0 = ldcg_f4(aPtr);           // h: cross-SM data -> L1 bypass
        float4 aR1 = ldcg_f4(aPtr + 4);
        float4 bR0 = *(const float4*)(bPtr);  // weights: L1-resident across steps
        float4 bR1 = *(const float4*)(bPtr + 4);
        float2 wR  = *(const float2*)(wPtr);

        // store tile 0 into buffer 0
        As[0][kh + 0][rl] = aR0.x;  As[0][kh + 1][rl] = aR0.y;
        As[0][kh + 2][rl] = aR0.z;  As[0][kh + 3][rl] = aR0.w;
        As[0][kh + 4][rl] = aR1.x;  As[0][kh + 5][rl] = aR1.y;
        As[0][kh + 6][rl] = aR1.z;  As[0][kh + 7][rl] = aR1.w;
        Bs[0][kh + 0][rl] = bR0.x;  Bs[0][kh + 1][rl] = bR0.y;
        Bs[0][kh + 2][rl] = bR0.z;  Bs[0][kh + 3][rl] = bR0.w;
        Bs[0][kh + 4][rl] = bR1.x;  Bs[0][kh + 5][rl] = bR1.y;
        Bs[0][kh + 6][rl] = bR1.z;  Bs[0][kh + 7][rl] = bR1.w;
        Ws[0][wk + 0][wrow] = wR.x;
        Ws[0][wk + 1][wrow] = wR.y;

        #pragma unroll 1
        for (int tt = 0; tt < HID / 16; tt++) {
            __syncthreads();           // buf filled -> visible; buf^1 free
            int buf = tt & 1;
            if (tt + 1 < HID / 16) {   // prefetch next tile from global
                int k0 = (tt + 1) * 16;
                aR0 = ldcg_f4(aPtr + k0);
                aR1 = ldcg_f4(aPtr + k0 + 4);
                bR0 = *(const float4*)(bPtr + k0);
                bR1 = *(const float4*)(bPtr + k0 + 4);
                wR  = *(const float2*)(wPtr + k0);
            }

            #pragma unroll
            for (int kk = 0; kk < 16; kk++) {
                float4 a0 = *(const float4*)&As[buf][kk][ty * 8];
                float4 a1 = *(const float4*)&As[buf][kk][ty * 8 + 4];
                unsigned long long A0 = pack2(a0.x, a0.x), A1 = pack2(a0.y, a0.y);
                unsigned long long A2 = pack2(a0.z, a0.z), A3 = pack2(a0.w, a0.w);
                unsigned long long A4 = pack2(a1.x, a1.x), A5 = pack2(a1.y, a1.y);
                unsigned long long A6 = pack2(a1.z, a1.z), A7 = pack2(a1.w, a1.w);
                #pragma unroll
                for (int g = 0; g < 4; g++) {
                    unsigned long long bv =
                        *(const unsigned long long*)&Bs[buf][kk][g * 32 + tx * 2];
                    fma2(acc[g][0], A0, bv);  fma2(acc[g][1], A1, bv);
                    fma2(acc[g][2], A2, bv);  fma2(acc[g][3], A3, bv);
                    fma2(acc[g][4], A4, bv);  fma2(acc[g][5], A5, bv);
                    fma2(acc[g][6], A6, bv);  fma2(acc[g][7], A7, bv);
                }
                unsigned long long wv =
                    *(const unsigned long long*)&Ws[buf][kk][tx * 2];
                fma2(accw[0], A0, wv);  fma2(accw[1], A1, wv);
                fma2(accw[2], A2, wv);  fma2(accw[3], A3, wv);
                fma2(accw[4], A4, wv);  fma2(accw[5], A5, wv);
                fma2(accw[6], A6, wv);  fma2(accw[7], A7, wv);
            }

            if (tt + 1 < HID / 16) {   // stage next tile into the other buffer
                int nb = buf ^ 1;
                As[nb][kh + 0][rl] = aR0.x;  As[nb][kh + 1][rl] = aR0.y;
                As[nb][kh + 2][rl] = aR0.z;  As[nb][kh + 3][rl] = aR0.w;
                As[nb][kh + 4][rl] = aR1.x;  As[nb][kh + 5][rl] = aR1.y;
                As[nb][kh + 6][rl] = aR1.z;  As[nb][kh + 7][rl] = aR1.w;
                Bs[nb][kh + 0][rl] = bR0.x;  Bs[nb][kh + 1][rl] = bR0.y;
                Bs[nb][kh + 2][rl] = bR0.z;  Bs[nb][kh + 3][rl] = bR0.w;
                Bs[nb][kh + 4][rl] = bR1.x;  Bs[nb][kh + 5][rl] = bR1.y;
                Bs[nb][kh + 6][rl] = bR1.z;  Bs[nb][kh + 7][rl] = bR1.w;
                Ws[nb][wk + 0][wrow] = wR.x;
                Ws[nb][wk + 1][wrow] = wR.y;
            }
        }

        // ---------- logits epilogue + sync1 (dead work at t=0: SOS forced) --
        if (t > 0) {
            #pragma unroll
            for (int m = 0; m < 8; m++) {
                int b = by * 128 + ty * 8 + m;
                float2 lw = unpack2(accw[m]);
                float x0 = lw.x + bb.x;
                float x1 = lw.y + bb.y;
                *(float2*)&out_prev[(size_t)b * VOC + colb] = make_float2(x0, x1);

                unsigned long long key = mkkey(x0, colb);
                unsigned long long k1  = mkkey(x1, colb + 1);
                if (k1 > key) key = k1;
                #pragma unroll
                for (int off = 8; off > 0; off >>= 1) {
                    unsigned long long o = __shfl_down_sync(0xFFFFFFFFu, key, off, 16);
                    if (o > key) key = o;
                }
                if (tx == 0) atomicMax(&g_key[parity][b], key);
            }

            // sync1: keys from all 16 jx CTAs of this b-tile
            __threadfence();
            __syncthreads();
            if (tid == 0) {
                atomicAdd(&g_d1[t][by], 1);
                while (ldcv_i32(&g_d1[t][by]) < 16) __nanosleep(32);
            }
            __syncthreads();
        }

        // ---------- LSTM epilogue + sync2 (dead at final step) --------------
        if (t < TSTEPS) {
            #pragma unroll
            for (int m = 0; m < 8; m++) {
                int b = by * 128 + ty * 8 + m;
                unsigned int row;
                if (t == 0) {
                    row = 0;  // SOS
                } else {
                    unsigned long long kv = ldcv_u64(&g_key[parity][b]);
                    row = 0xFFFFFFFFu - (unsigned int)kv;
                }
                const float* ep = g_EProj + (size_t)row * FH + jBase;

                float2 gi = unpack2(acc[0][m]);
                float2 gf = unpack2(acc[1][m]);
                float2 gg = unpack2(acc[2][m]);
                float2 go = unpack2(acc[3][m]);
                float2 e;
                e = *(const float2*)(ep +    0); gi.x += e.x; gi.y += e.y;
                e = *(const float2*)(ep +  512); gf.x += e.x; gf.y += e.y;
                e = *(const float2*)(ep + 1024); gg.x += e.x; gg.y += e.y;
                e = *(const float2*)(ep + 1536); go.x += e.x; go.y += e.y;

                float2 cold = *(const float2*)&g_c[(size_t)b * HID + jBase];
                float2 cn, hn;
                {
                    float i_ = sigfast(gi.x), f_ = sigfast(gf.x);
                    float gv = tanhfast(gg.x), o_ = sigfast(go.x);
                    cn.x = f_ * cold.x + i_ * gv;
                    hn.x = o_ * tanhfast(cn.x);
                }
                {
                    float i_ = sigfast(gi.y), f_ = sigfast(gf.y);
                    float gv = tanhfast(gg.y), o_ = sigfast(go.y);
                    cn.y = f_ * cold.y + i_ * gv;
                    hn.y = o_ * tanhfast(cn.y);
                }
                *(float2*)&g_c[(size_t)b * HID + jBase] = cn;   // CTA-private
                stcg_f2(&h_out[(size_t)b * HID + jBase], hn.x, hn.y);  // cross-SM
            }

            // sync2: h(t+1) of this b-tile fully written (full barrier as R11)
            __threadfence();
            __syncthreads();
            if (tid == 0) {
                atomicAdd(&g_d2[t][by], 1);
                while (ldcv_i32(&g_d2[t][by]) < 16) __nanosleep(32);
            }
            __syncthreads();
        }
    }
}

// ============================================================
// launch: init, eproj, ONE persistent kernel for all 65 steps
// ============================================================
extern "C" void kernel_launch(void* const* d_in, const int* in_sizes, int n_in,
                              void* d_out, int out_size)
{
    int i = 0;
    while (i < n_in && in_sizes[i] != BATCH * HID) i++;
    const float* enc_h = (const float*)d_in[i];
    const float* enc_c = (const float*)d_in[i + 1];
    const float* emb   = (const float*)d_in[i + 2];
    const float* W_ih  = (const float*)d_in[i + 3];
    const float* W_hh  = (const float*)d_in[i + 4];
    const float* b_ih  = (const float*)d_in[i + 5];
    const float* b_hh  = (const float*)d_in[i + 6];
    const float* W_out = (const float*)d_in[i + 7];
    const float* b_out = (const float*)d_in[i + 8];
    float* out = (float*)d_out;

    init_kernel<<<512, 256>>>(enc_h, enc_c);
    eproj_kernel<<<dim3(16, 4), 256>>>(emb, W_ih, b_ih, b_hh);
    step_persist_kernel<<<dim3(16, 8), 256>>>(W_hh, W_out, b_out, out);
}